// round 12
// baseline (speedup 1.0000x reference)
#include <cuda_runtime.h>
#include <cuda_bf16.h>

// Problem shape (fixed by the benchmark's setup_inputs): B=8, S=4096, D=512.
#define BB 8
#define SS 4096
#define DD 512
#define QPR (DD / 4)          // 128 float4-quads per (s) row

#define P_DROP 0.1f
#define INV_KEEP (1.0f / 0.9f)

#define BLOCK_THR 512         // single-variable probe vs the 256-thread champion

// r1 = 10000^(-1/256) split into a float-float pair at COMPILE time.
constexpr double R1d   = 0.9646616199111541;
constexpr float  R1_HI = (float)R1d;
constexpr float  R1_LO = (float)(R1d - (double)R1_HI);

// Cody-Waite 2*pi split: C1 = 12868/2^11 (13 mantissa bits, so k*C1 with
// k <= 652 is EXACT in fp32), C2 = 2*pi - C1.
#define TWO_PI_C1  6.283203125f
#define TWO_PI_C2 (-1.7817820413524e-5f)
#define INV_2PI    0.15915494309189535f

// float-float multiply: value = hi + lo, all on the fp32 FMA pipe (no fp64).
__device__ __forceinline__ float2 dfmul(float2 a, float2 b) {
    float p = a.x * b.x;
    float e = __fmaf_rn(a.x, b.x, -p);     // exact low part of a.hi*b.hi
    e = __fmaf_rn(a.x, b.y, e);
    e = __fmaf_rn(a.y, b.x, e);
    float hi = p + e;
    float lo = e - (hi - p);
    return make_float2(hi, lo);
}

// angle = s * w (float-float), reduced mod 2*pi into ~[-pi, pi].
__device__ __forceinline__ float reduced_angle(float s_f, float2 w) {
    float ahi = s_f * w.x;
    float err = __fmaf_rn(s_f, w.x, -ahi);       // exact product correction
    float alo = __fmaf_rn(s_f, w.y, err);
    float k   = rintf(ahi * INV_2PI);            // k <= 652
    float t   = __fmaf_rn(-k, TWO_PI_C1, ahi);   // exact (C1 has 13 bits)
    t = __fmaf_rn(-k, TWO_PI_C2, t);
    return t + alo;
}

// Champion structure (R9/R11): natural regs (32), evict-first (__ldcs) loads
// on the single-use input streams, DEFAULT-policy stores for L2 write
// combining, fp32 float-float PE + MUFU sin/cos, batch-amortized 8x.
// Only change this round: 512-thread CTAs (grid 1024).
__global__ void __launch_bounds__(BLOCK_THR) pe_dropout_kernel(
    const float* __restrict__ x,
    const float* __restrict__ drop_mask,
    float* __restrict__ out)
{
    const int t = blockIdx.x * BLOCK_THR + threadIdx.x;    // 0 .. SS*QPR-1
    const int q = t & (QPR - 1);                           // quad within row
    const int s = t >> 7;                                  // row (QPR == 128)

    // ---- w = r1^(4q) via float-float squaring chain (fp32 pipe) ----
    const float2 r1 = make_float2(R1_HI, R1_LO);
    float2 p = dfmul(r1, r1);  p = dfmul(p, p);            // r1^4
    float2 w = make_float2(1.0f, 0.0f);
    #pragma unroll
    for (int k = 0; k < 7; k++) {                          // q has 7 bits
        if (q & (1 << k)) w = dfmul(w, p);
        p = dfmul(p, p);
    }
    const float2 w1 = dfmul(w,  r1);
    const float2 w2 = dfmul(w1, r1);
    const float2 w3 = dfmul(w2, r1);

    const float s_f = (float)s;
    const float pe0 = __sinf(reduced_angle(s_f, w));       // even d -> sin
    const float pe1 = __cosf(reduced_angle(s_f, w1));      // odd  d -> cos
    const float pe2 = __sinf(reduced_angle(s_f, w2));
    const float pe3 = __cosf(reduced_angle(s_f, w3));

    size_t idx = (size_t)s * DD + q * 4;                   // offset in one batch slice
    const size_t batch_stride = (size_t)SS * DD;

    #pragma unroll
    for (int b = 0; b < BB; b++) {
        const float4 xv = __ldcs(reinterpret_cast<const float4*>(x + idx));
        const float4 mv = __ldcs(reinterpret_cast<const float4*>(drop_mask + idx));
        float4 o;
        o.x = (xv.x + pe0) * (mv.x >= P_DROP ? INV_KEEP : 0.0f);
        o.y = (xv.y + pe1) * (mv.y >= P_DROP ? INV_KEEP : 0.0f);
        o.z = (xv.z + pe2) * (mv.z >= P_DROP ? INV_KEEP : 0.0f);
        o.w = (xv.w + pe3) * (mv.w >= P_DROP ? INV_KEEP : 0.0f);
        *reinterpret_cast<float4*>(out + idx) = o;
        idx += batch_stride;
    }
}

extern "C" void kernel_launch(void* const* d_in, const int* in_sizes, int n_in,
                              void* d_out, int out_size)
{
    const float* x         = (const float*)d_in[0];
    const float* drop_mask = (const float*)d_in[1];
    float*       out       = (float*)d_out;

    const int n_quads = SS * QPR;                          // 524288 threads
    const int grid    = n_quads / BLOCK_THR;               // 1024 blocks
    pe_dropout_kernel<<<grid, BLOCK_THR>>>(x, drop_mask, out);
}

// round 13
// speedup vs baseline: 1.0010x; 1.0010x over previous
#include <cuda_runtime.h>
#include <cuda_bf16.h>

// Problem shape (fixed by the benchmark's setup_inputs): B=8, S=4096, D=512.
#define BB 8
#define SS 4096
#define DD 512
#define QPR (DD / 4)          // 128 float4-quads per (s) row

#define P_DROP 0.1f
#define INV_KEEP (1.0f / 0.9f)

#define BLOCK_THR 1024        // final block-size sweep point: 2 CTAs/SM x 32 warps

// r1 = 10000^(-1/256) split into a float-float pair at COMPILE time.
constexpr double R1d   = 0.9646616199111541;
constexpr float  R1_HI = (float)R1d;
constexpr float  R1_LO = (float)(R1d - (double)R1_HI);

// Cody-Waite 2*pi split: C1 = 12868/2^11 (13 mantissa bits, so k*C1 with
// k <= 652 is EXACT in fp32), C2 = 2*pi - C1.
#define TWO_PI_C1  6.283203125f
#define TWO_PI_C2 (-1.7817820413524e-5f)
#define INV_2PI    0.15915494309189535f

// float-float multiply: value = hi + lo, all on the fp32 FMA pipe (no fp64).
__device__ __forceinline__ float2 dfmul(float2 a, float2 b) {
    float p = a.x * b.x;
    float e = __fmaf_rn(a.x, b.x, -p);     // exact low part of a.hi*b.hi
    e = __fmaf_rn(a.x, b.y, e);
    e = __fmaf_rn(a.y, b.x, e);
    float hi = p + e;
    float lo = e - (hi - p);
    return make_float2(hi, lo);
}

// angle = s * w (float-float), reduced mod 2*pi into ~[-pi, pi].
__device__ __forceinline__ float reduced_angle(float s_f, float2 w) {
    float ahi = s_f * w.x;
    float err = __fmaf_rn(s_f, w.x, -ahi);       // exact product correction
    float alo = __fmaf_rn(s_f, w.y, err);
    float k   = rintf(ahi * INV_2PI);            // k <= 652
    float t   = __fmaf_rn(-k, TWO_PI_C1, ahi);   // exact (C1 has 13 bits)
    t = __fmaf_rn(-k, TWO_PI_C2, t);
    return t + alo;
}

// Champion structure (R9/R11/R12): natural regs (32), evict-first (__ldcs)
// loads on the single-use input streams, DEFAULT-policy stores for L2 write
// combining, fp32 float-float PE + MUFU sin/cos, batch-amortized 8x.
// Only change this round: 1024-thread CTAs (grid 512) for 64-warp/SM packing.
__global__ void __launch_bounds__(BLOCK_THR) pe_dropout_kernel(
    const float* __restrict__ x,
    const float* __restrict__ drop_mask,
    float* __restrict__ out)
{
    const int t = blockIdx.x * BLOCK_THR + threadIdx.x;    // 0 .. SS*QPR-1
    const int q = t & (QPR - 1);                           // quad within row
    const int s = t >> 7;                                  // row (QPR == 128)

    // ---- w = r1^(4q) via float-float squaring chain (fp32 pipe) ----
    const float2 r1 = make_float2(R1_HI, R1_LO);
    float2 p = dfmul(r1, r1);  p = dfmul(p, p);            // r1^4
    float2 w = make_float2(1.0f, 0.0f);
    #pragma unroll
    for (int k = 0; k < 7; k++) {                          // q has 7 bits
        if (q & (1 << k)) w = dfmul(w, p);
        p = dfmul(p, p);
    }
    const float2 w1 = dfmul(w,  r1);
    const float2 w2 = dfmul(w1, r1);
    const float2 w3 = dfmul(w2, r1);

    const float s_f = (float)s;
    const float pe0 = __sinf(reduced_angle(s_f, w));       // even d -> sin
    const float pe1 = __cosf(reduced_angle(s_f, w1));      // odd  d -> cos
    const float pe2 = __sinf(reduced_angle(s_f, w2));
    const float pe3 = __cosf(reduced_angle(s_f, w3));

    size_t idx = (size_t)s * DD + q * 4;                   // offset in one batch slice
    const size_t batch_stride = (size_t)SS * DD;

    #pragma unroll
    for (int b = 0; b < BB; b++) {
        const float4 xv = __ldcs(reinterpret_cast<const float4*>(x + idx));
        const float4 mv = __ldcs(reinterpret_cast<const float4*>(drop_mask + idx));
        float4 o;
        o.x = (xv.x + pe0) * (mv.x >= P_DROP ? INV_KEEP : 0.0f);
        o.y = (xv.y + pe1) * (mv.y >= P_DROP ? INV_KEEP : 0.0f);
        o.z = (xv.z + pe2) * (mv.z >= P_DROP ? INV_KEEP : 0.0f);
        o.w = (xv.w + pe3) * (mv.w >= P_DROP ? INV_KEEP : 0.0f);
        *reinterpret_cast<float4*>(out + idx) = o;
        idx += batch_stride;
    }
}

extern "C" void kernel_launch(void* const* d_in, const int* in_sizes, int n_in,
                              void* d_out, int out_size)
{
    const float* x         = (const float*)d_in[0];
    const float* drop_mask = (const float*)d_in[1];
    float*       out       = (float*)d_out;

    const int n_quads = SS * QPR;                          // 524288 threads
    const int grid    = n_quads / BLOCK_THR;               // 512 blocks
    pe_dropout_kernel<<<grid, BLOCK_THR>>>(x, drop_mask, out);
}